// round 15
// baseline (speedup 1.0000x reference)
#include <cuda_runtime.h>
#include <cuda_bf16.h>
#include <math.h>
#include <stdint.h>

// Problem constants
#define NN 10000      // nodes
#define NPAD 10112    // padded rows (multiple of 128)
#define EE 100000     // raw edges
#define ET 110000     // edges + self loops
#define CC 200        // channels per head

// B arena layout (elems): L0 800x224 | L1-3 800x800 | L4 240x800
#define BOFF0 0
#define BOFF1 179200
#define BOFF2 819200
#define BOFF3 1459200
#define BOFF4 2099200
#define BTOT  2291200

// ---------------- device scratch ----------------
__device__ __align__(16) float g_h[NN * 800];
__device__ __align__(256) __nv_bfloat16 g_ahi[NPAD * 800];
__device__ __align__(256) __nv_bfloat16 g_alo[NPAD * 800];
__device__ __align__(256) __nv_bfloat16 g_bhi[BTOT];
__device__ __align__(256) __nv_bfloat16 g_blo[BTOT];
__device__ float g_asrcb[2][NN * 4];   // ping-pong alpha accumulators
__device__ float g_adstb[2][NN * 4];
__device__ int   g_deg[NN];
__device__ int   g_rowptr[NN + 1];
__device__ int   g_cursor[NN];
__device__ int   g_srcs[ET];
__device__ int   g_eid[ET];

static inline int div_up(int a, int b) { return (a + b - 1) / b; }

// ================= PTX helpers (base ISA only) =================
__device__ __forceinline__ uint32_t smem_u32(const void* p) {
    uint32_t a;
    asm("{ .reg .u64 t; cvta.to.shared.u64 t, %1; cvt.u32.u64 %0, t; }" : "=r"(a) : "l"(p));
    return a;
}
#define CP_ASYNC16(dst, src) \
    asm volatile("cp.async.cg.shared.global [%0], [%1], 16;" :: "r"(dst), "l"(src))
#define CP_COMMIT asm volatile("cp.async.commit_group;" ::: "memory")
#define CP_WAIT1  asm volatile("cp.async.wait_group 1;" ::: "memory")
#define CP_WAIT0  asm volatile("cp.async.wait_group 0;" ::: "memory")

__device__ __forceinline__ void ldsm_x4(uint32_t* r, uint32_t addr) {
    asm volatile("ldmatrix.sync.aligned.m8n8.x4.shared.b16 {%0,%1,%2,%3}, [%4];"
        : "=r"(r[0]), "=r"(r[1]), "=r"(r[2]), "=r"(r[3]) : "r"(addr));
}
__device__ __forceinline__ void ldsm_x2(uint32_t* r, uint32_t addr) {
    asm volatile("ldmatrix.sync.aligned.m8n8.x2.shared.b16 {%0,%1}, [%2];"
        : "=r"(r[0]), "=r"(r[1]) : "r"(addr));
}
__device__ __forceinline__ void mma_bf16(float* d, const uint32_t* a, const uint32_t* b) {
    asm volatile("mma.sync.aligned.m16n8k16.row.col.f32.bf16.bf16.f32 "
        "{%0,%1,%2,%3}, {%4,%5,%6,%7}, {%8,%9}, {%0,%1,%2,%3};"
        : "+f"(d[0]), "+f"(d[1]), "+f"(d[2]), "+f"(d[3])
        : "r"(a[0]), "r"(a[1]), "r"(a[2]), "r"(a[3]), "r"(b[0]), "r"(b[1]));
}

// ---------------- CSR build ----------------
__global__ void zero_deg_kernel() {
    int i = blockIdx.x * blockDim.x + threadIdx.x;
    if (i < NN) g_deg[i] = 0;
}
__global__ void hist_kernel(const int* __restrict__ ei) {
    int e = blockIdx.x * blockDim.x + threadIdx.x;
    if (e >= ET) return;
    int d = (e < EE) ? ei[EE + e] : (e - EE);
    atomicAdd(&g_deg[d], 1);
}
// scan also initializes g_cursor
__global__ void scan_kernel() {
    __shared__ int sh[1024];
    __shared__ int carry;
    int tid = threadIdx.x;
    if (tid == 0) carry = 0;
    __syncthreads();
    for (int base = 0; base < NN; base += 1024) {
        int i = base + tid;
        int v = (i < NN) ? g_deg[i] : 0;
        int x = v;
        #pragma unroll
        for (int off = 1; off < 1024; off <<= 1) {
            sh[tid] = x;
            __syncthreads();
            if (tid >= off) x += sh[tid - off];
            __syncthreads();
        }
        if (i < NN) {
            int ex = carry + x - v;
            g_rowptr[i] = ex;
            g_cursor[i] = ex;
        }
        sh[tid] = x;
        __syncthreads();
        int total = sh[1023];
        __syncthreads();
        if (tid == 0) carry += total;
        __syncthreads();
    }
    if (threadIdx.x == 0) g_rowptr[NN] = carry;
}
__global__ void scatter_kernel(const int* __restrict__ ei) {
    int e = blockIdx.x * blockDim.x + threadIdx.x;
    if (e >= ET) return;
    int s, d;
    if (e < EE) { s = ei[e]; d = ei[EE + e]; }
    else        { s = e - EE; d = e - EE; }
    int pos = atomicAdd(&g_cursor[d], 1);
    g_srcs[pos] = s;
    g_eid[pos]  = e;
}

// ---------------- bf16 hi/lo prep ----------------
__device__ __forceinline__ void bf16_split(float v, __nv_bfloat16& h, __nv_bfloat16& l) {
    h = __float2bfloat16(v);
    l = __float2bfloat16(v - __bfloat162float(h));
}

// L0: X -> g_ahi/g_alo (Kp=224 layout) AND zero pad rows for the 800 layout
__global__ void prep_a_kernel(const float* __restrict__ A, int K, int Kp) {
    int idx = blockIdx.x * blockDim.x + threadIdx.x;
    int n0 = NPAD * Kp;
    int n1 = (NPAD - NN) * 800;
    if (idx < n0) {
        int row = idx / Kp;
        int k = idx - row * Kp;
        float v = (row < NN && k < K) ? A[(size_t)row * K + k] : 0.f;
        __nv_bfloat16 h, l;
        bf16_split(v, h, l);
        g_ahi[idx] = h;
        g_alo[idx] = l;
    }
    if (idx < n1) {
        int off = NN * 800 + idx;
        if (off >= n0) {
            g_ahi[off] = __float2bfloat16(0.f);
            g_alo[off] = __float2bfloat16(0.f);
        }
    }
}

// ONE kernel: transpose/split all 5 weight matrices into the Bt arena,
// and zero both alpha ping-pong buffer pairs.
__global__ void prep_all_b_kernel(
    const float* __restrict__ W0, const float* __restrict__ W1,
    const float* __restrict__ W2, const float* __restrict__ W3,
    const float* __restrict__ W4)
{
    int idx = blockIdx.x * blockDim.x + threadIdx.x;
    if (idx < 2 * NN * 4) {
        int b = idx / (NN * 4), r = idx - b * (NN * 4);
        g_asrcb[b][r] = 0.f;
        g_adstb[b][r] = 0.f;
    }
    if (idx >= BTOT) return;
    const float* W;
    int off, Kp, K, HC;
    if (idx < BOFF1)      { W = W0; off = BOFF0; Kp = 224; K = 200; HC = 800; }
    else if (idx < BOFF2) { W = W1; off = BOFF1; Kp = 800; K = 800; HC = 800; }
    else if (idx < BOFF3) { W = W2; off = BOFF2; Kp = 800; K = 800; HC = 800; }
    else if (idx < BOFF4) { W = W3; off = BOFF3; Kp = 800; K = 800; HC = 800; }
    else                  { W = W4; off = BOFF4; Kp = 800; K = 800; HC = 200; }
    int rem = idx - off;
    int n = rem / Kp;
    int k = rem - n * Kp;
    float v = (n < HC && k < K) ? W[(size_t)k * HC + n] : 0.f;
    __nv_bfloat16 hi, lo;
    bf16_split(v, hi, lo);
    g_bhi[idx] = hi;
    g_blo[idx] = lo;
}

// ================= mma.sync bf16-split GEMM =================
// Block tile 128(M) x 80(N), 8 warps = 4m x 2n, warp tile 32x40.
// 3-stage cp.async pipeline, one __syncthreads per K-iteration.
// Alpha dots via head-split buckets + atomicAdd into the current ping buffer.
// Each block also zeroes a slice of the PARTNER buffers (used by next GEMM).
#define SA_LO 8192u
#define SB_HI 16384u
#define SB_LO 21504u
#define STAGE 26624u
#define NSTAGE 3
#define CSTRIDE 88
#define GEMM_SMEM (NSTAGE * 26624)

__device__ __forceinline__ uint32_t swz(int r, int c) {
    return (uint32_t)(r * 64 + ((c ^ ((r >> 1) & 3)) << 4));
}

__device__ __forceinline__ void fill_stage(
    uint32_t su, int buf, int k0,
    const __nv_bfloat16* __restrict__ ahi, const __nv_bfloat16* __restrict__ alo,
    const __nv_bfloat16* __restrict__ bh, const __nv_bfloat16* __restrict__ bl,
    int Kp, int row0, int tid)
{
    uint32_t sb = su + (uint32_t)buf * STAGE;
    #pragma unroll
    for (int it = 0; it < 2; it++) {
        int j = tid + it * 256;
        int r = j >> 2, c = j & 3;
        uint32_t da = sb + swz(r, c);
        const char* sa = (const char*)(ahi + (size_t)(row0 + r) * Kp + k0) + c * 16;
        CP_ASYNC16(da, sa);
        const char* sl = (const char*)(alo + (size_t)(row0 + r) * Kp + k0) + c * 16;
        CP_ASYNC16(da + SA_LO, sl);
    }
    #pragma unroll
    for (int j0 = 0; j0 < 320; j0 += 256) {
        int j = j0 + tid;
        if (j < 320) {
            int r = j >> 2, c = j & 3;
            uint32_t db = sb + SB_HI + swz(r, c);
            const char* sh = (const char*)(bh + (size_t)r * Kp + k0) + c * 16;
            CP_ASYNC16(db, sh);
            const char* sl = (const char*)(bl + (size_t)r * Kp + k0) + c * 16;
            CP_ASYNC16(db + (SB_LO - SB_HI), sl);
        }
    }
}

__device__ __forceinline__ void load_b_frags(
    uint32_t bb[5][2], uint32_t sb, uint32_t plane_off, int kk, int nw, int lane)
{
    int g = lane >> 3;
    #pragma unroll
    for (int p = 0; p < 2; p++) {
        int nf = p * 2;
        int r = nw * 40 + (nf + (g >> 1)) * 8 + (lane & 7);
        int ch = 2 * kk + (g & 1);
        uint32_t addr = sb + SB_HI + plane_off + swz(r, ch);
        uint32_t t[4];
        ldsm_x4(t, addr);
        bb[nf][0] = t[0]; bb[nf][1] = t[1];
        bb[nf + 1][0] = t[2]; bb[nf + 1][1] = t[3];
    }
    int r = nw * 40 + 32 + (lane & 7);
    int ch = 2 * kk + ((lane >> 3) & 1);
    ldsm_x2(bb[4], sb + SB_HI + plane_off + swz(r, ch));
}

__global__ __launch_bounds__(256, 2) void gemm_mma_kernel(
    const __nv_bfloat16* __restrict__ Ahi, const __nv_bfloat16* __restrict__ Alo,
    const __nv_bfloat16* __restrict__ Bhi, const __nv_bfloat16* __restrict__ Blo,
    float* __restrict__ C,
    const float* __restrict__ asv_g, const float* __restrict__ adv_g,
    float* __restrict__ asrc_o, float* __restrict__ adst_o,
    float* __restrict__ zsrc, float* __restrict__ zdst,   // partner buffers to zero
    int Kp, int HC, int H)
{
    extern __shared__ char smem[];
    uint32_t su = smem_u32(smem);
    int tid = threadIdx.x;
    int w = tid >> 5, lane = tid & 31;
    int mw = w >> 1, nw = w & 1;
    int bm = blockIdx.x, bn = blockIdx.y;
    int row0 = bm * 128;
    int col0 = bn * 80;

    // zero a slice of the partner alpha buffers (stream-ordered vs their users)
    {
        int G = gridDim.x * gridDim.y;
        int bid = bn * gridDim.x + bm;
        for (int i = bid * 256 + tid; i < NN * 4; i += G * 256) {
            zsrc[i] = 0.f;
            zdst[i] = 0.f;
        }
    }

    const __nv_bfloat16* bhp = Bhi + (size_t)col0 * Kp;
    const __nv_bfloat16* blp = Blo + (size_t)col0 * Kp;

    float acc[2][5][4];
    #pragma unroll
    for (int mf = 0; mf < 2; mf++)
        #pragma unroll
        for (int nf = 0; nf < 5; nf++)
            #pragma unroll
            for (int q = 0; q < 4; q++) acc[mf][nf][q] = 0.f;

    int niter = Kp >> 5;
    fill_stage(su, 0, 0, Ahi, Alo, bhp, blp, Kp, row0, tid);
    CP_COMMIT;
    fill_stage(su, 1, 32, Ahi, Alo, bhp, blp, Kp, row0, tid);
    CP_COMMIT;

    for (int i = 0; i < niter; i++) {
        CP_WAIT1;
        __syncthreads();
        if (i + 2 < niter)
            fill_stage(su, (i + 2) % NSTAGE, (i + 2) * 32,
                       Ahi, Alo, bhp, blp, Kp, row0, tid);
        CP_COMMIT;

        uint32_t sb = su + (uint32_t)(i % NSTAGE) * STAGE;
        #pragma unroll
        for (int kk = 0; kk < 2; kk++) {
            uint32_t ah[2][4], al[2][4];
            #pragma unroll
            for (int mf = 0; mf < 2; mf++) {
                int r = mw * 32 + mf * 16 + (lane & 7) + ((lane >> 3) & 1) * 8;
                int ch = 2 * kk + (lane >> 4);
                uint32_t addr = sb + swz(r, ch);
                ldsm_x4(ah[mf], addr);
                ldsm_x4(al[mf], addr + SA_LO);
            }
            uint32_t bb[5][2];
            load_b_frags(bb, sb, 0u, kk, nw, lane);
            #pragma unroll
            for (int nf = 0; nf < 5; nf++)
                #pragma unroll
                for (int mf = 0; mf < 2; mf++)
                    mma_bf16(acc[mf][nf], ah[mf], bb[nf]);
            #pragma unroll
            for (int nf = 0; nf < 5; nf++)
                #pragma unroll
                for (int mf = 0; mf < 2; mf++)
                    mma_bf16(acc[mf][nf], al[mf], bb[nf]);
            load_b_frags(bb, sb, SB_LO - SB_HI, kk, nw, lane);
            #pragma unroll
            for (int nf = 0; nf < 5; nf++)
                #pragma unroll
                for (int mf = 0; mf < 2; mf++)
                    mma_bf16(acc[mf][nf], ah[mf], bb[nf]);
        }
    }
    CP_WAIT0;
    __syncthreads();

    // ---- epilogue: frags -> smem ----
    float* Cs = (float*)smem;
    #pragma unroll
    for (int mf = 0; mf < 2; mf++) {
        #pragma unroll
        for (int nf = 0; nf < 5; nf++) {
            int r0 = mw * 32 + mf * 16 + (lane >> 2);
            int cb = nw * 40 + nf * 8 + 2 * (lane & 3);
            *(float2*)&Cs[r0 * CSTRIDE + cb] = make_float2(acc[mf][nf][0], acc[mf][nf][1]);
            *(float2*)&Cs[(r0 + 8) * CSTRIDE + cb] = make_float2(acc[mf][nf][2], acc[mf][nf][3]);
        }
    }
    __syncthreads();

    // alpha dots with head-split buckets; warp w handles rows w*16..w*16+15
    int h0 = col0 / CC;
    int hb = (h0 + 1) * CC - col0;
    #pragma unroll
    for (int i = 0; i < 16; i++) {
        int r = w * 16 + i;
        int gr = row0 + r;
        float sa0 = 0.f, sa1 = 0.f, sd0 = 0.f, sd1 = 0.f;
        #pragma unroll
        for (int cc = 0; cc < 3; cc++) {
            int c = lane + cc * 32;
            int gc = col0 + c;
            if (c < 80 && gc < HC) {
                float v = Cs[r * CSTRIDE + c];
                float pa = v * __ldg(asv_g + gc);
                float pd = v * __ldg(adv_g + gc);
                if (c < hb) { sa0 += pa; sd0 += pd; }
                else        { sa1 += pa; sd1 += pd; }
            }
        }
        #pragma unroll
        for (int o = 16; o; o >>= 1) {
            sa0 += __shfl_xor_sync(0xffffffffu, sa0, o);
            sa1 += __shfl_xor_sync(0xffffffffu, sa1, o);
            sd0 += __shfl_xor_sync(0xffffffffu, sd0, o);
            sd1 += __shfl_xor_sync(0xffffffffu, sd1, o);
        }
        if (lane == 0 && gr < NN) {
            atomicAdd(&asrc_o[gr * H + h0], sa0);
            atomicAdd(&adst_o[gr * H + h0], sd0);
            if (hb < 80 && h0 + 1 < H) {
                atomicAdd(&asrc_o[gr * H + h0 + 1], sa1);
                atomicAdd(&adst_o[gr * H + h0 + 1], sd1);
            }
        }
    }

    // coalesced store of real columns
    for (int idx = tid; idx < 128 * 80; idx += 256) {
        int r = idx / 80;
        int c = idx - r * 80;
        int gr = row0 + r;
        int gc = col0 + c;
        if (gr < NN && gc < HC)
            C[(size_t)gr * HC + gc] = Cs[r * CSTRIDE + c];
    }
}

// ---------------- segment softmax + aggregation: one warp per (node, head) ----------------
// Single-pass online softmax with accumulator rescaling; float4 feature gather;
// 1-ahead prefetch of the dependent srcs->asrc chain.
__global__ __launch_bounds__(256) void agg_warp_kernel(
    const float* __restrict__ hfeat, const float* __restrict__ bias,
    const float* __restrict__ asrc, const float* __restrict__ adst,
    float* __restrict__ out, float* __restrict__ attn,
    __nv_bfloat16* __restrict__ ahi_o, __nv_bfloat16* __restrict__ alo_o,
    int H, int HC)
{
    int gw = (blockIdx.x * blockDim.x + threadIdx.x) >> 5;
    int lane = threadIdx.x & 31;
    if (gw >= NN * H) return;
    int n = gw / H;
    int h = gw - n * H;

    int start = g_rowptr[n];
    int end   = g_rowptr[n + 1];
    float adn = adst[n * H + h];

    int c40 = lane;           // always < 50
    int c41 = 32 + lane;
    bool act1 = (c41 < 50);

    float m = -1e30f, den = 0.f;
    float4 A0 = make_float4(0.f, 0.f, 0.f, 0.f);
    float4 A1 = A0;

    int s_nxt = 0; float as_nxt = 0.f;
    if (start < end) {
        s_nxt = __ldg(&g_srcs[start]);
        as_nxt = __ldg(&asrc[s_nxt * H + h]);
    }
    for (int j = start; j < end; j++) {
        int s = s_nxt;
        float e = as_nxt + adn;
        if (j + 1 < end) {
            s_nxt = __ldg(&g_srcs[j + 1]);
            as_nxt = __ldg(&asrc[s_nxt * H + h]);
        }
        e = (e > 0.f) ? e : 0.2f * e;
        float mn = fmaxf(m, e);
        float sc = expf(m - mn);
        float p  = expf(e - mn);
        den = den * sc + p;
        const float* hp = hfeat + (size_t)s * HC + h * CC;
        float4 v0 = *(const float4*)(hp + 4 * c40);
        A0.x = A0.x * sc + p * v0.x;
        A0.y = A0.y * sc + p * v0.y;
        A0.z = A0.z * sc + p * v0.z;
        A0.w = A0.w * sc + p * v0.w;
        if (act1) {
            float4 v1 = *(const float4*)(hp + 4 * c41);
            A1.x = A1.x * sc + p * v1.x;
            A1.y = A1.y * sc + p * v1.y;
            A1.z = A1.z * sc + p * v1.z;
            A1.w = A1.w * sc + p * v1.w;
        }
        m = mn;
    }
    float invden = 1.f / den;

    // attn (last layer only): short second sweep with final (m, invden)
    if (attn && lane == 0) {
        for (int j = start; j < end; j++) {
            int s = __ldg(&g_srcs[j]);
            float e = __ldg(&asrc[s * H + h]) + adn;
            e = (e > 0.f) ? e : 0.2f * e;
            attn[__ldg(&g_eid[j])] = expf(e - m) * invden;
        }
    }

    // epilogue: normalize + bias + GELU + vectorized outputs
    const float kc = 0.70710678118654752f;
    #pragma unroll
    for (int k = 0; k < 2; k++) {
        int c4 = (k == 0) ? c40 : c41;
        if (k == 1 && !act1) break;
        float4 a = (k == 0) ? A0 : A1;
        float4 b4 = *(const float4*)&bias[h * CC + 4 * c4];
        float4 o4;
        o4.x = a.x * invden + b4.x;
        o4.y = a.y * invden + b4.y;
        o4.z = a.z * invden + b4.z;
        o4.w = a.w * invden + b4.w;
        o4.x = 0.5f * o4.x * (1.f + erff(o4.x * kc));
        o4.y = 0.5f * o4.y * (1.f + erff(o4.y * kc));
        o4.z = 0.5f * o4.z * (1.f + erff(o4.z * kc));
        o4.w = 0.5f * o4.w * (1.f + erff(o4.w * kc));
        if (out) *(float4*)&out[(size_t)n * HC + h * CC + 4 * c4] = o4;
        if (ahi_o) {
            size_t base = (size_t)n * 800 + h * CC + 4 * c4;
            __nv_bfloat16 hx, lx, hy, ly, hz, lz, hw, lw;
            bf16_split(o4.x, hx, lx); bf16_split(o4.y, hy, ly);
            bf16_split(o4.z, hz, lz); bf16_split(o4.w, hw, lw);
            *(__nv_bfloat162*)&ahi_o[base]     = __nv_bfloat162(hx, hy);
            *(__nv_bfloat162*)&ahi_o[base + 2] = __nv_bfloat162(hz, hw);
            *(__nv_bfloat162*)&alo_o[base]     = __nv_bfloat162(lx, ly);
            *(__nv_bfloat162*)&alo_o[base + 2] = __nv_bfloat162(lz, lw);
        }
    }
}

// ---------------- host launch ----------------
extern "C" void kernel_launch(void* const* d_in, const int* in_sizes, int n_in,
                              void* d_out, int out_size)
{
    const float* X  = (const float*)d_in[0];
    const int*   ei = (const int*)d_in[1];
    const float *W[5], *AS[5], *AD[5], *Bb[5];
    for (int i = 0; i < 5; i++) {
        W[i]  = (const float*)d_in[2 + 4 * i];
        AS[i] = (const float*)d_in[3 + 4 * i];
        AD[i] = (const float*)d_in[4 + 4 * i];
        Bb[i] = (const float*)d_in[5 + 4 * i];
    }
    float* out_x = (float*)d_out;
    float* out_a = out_x + (size_t)NN * 200;

    float *ph;
    float *pasrc[2], *padst[2];
    __nv_bfloat16 *pahi, *palo, *pbhi, *pblo;
    cudaGetSymbolAddress((void**)&ph,  g_h);
    cudaGetSymbolAddress((void**)&pahi, g_ahi);
    cudaGetSymbolAddress((void**)&palo, g_alo);
    cudaGetSymbolAddress((void**)&pbhi, g_bhi);
    cudaGetSymbolAddress((void**)&pblo, g_blo);
    {
        float* base;
        cudaGetSymbolAddress((void**)&base, g_asrcb);
        pasrc[0] = base; pasrc[1] = base + NN * 4;
        cudaGetSymbolAddress((void**)&base, g_adstb);
        padst[0] = base; padst[1] = base + NN * 4;
    }

    cudaFuncSetAttribute(gemm_mma_kernel, cudaFuncAttributeMaxDynamicSharedMemorySize, GEMM_SMEM);

    // ---- CSR build + prep ----
    zero_deg_kernel<<<div_up(NN, 256), 256>>>();
    hist_kernel<<<div_up(ET, 256), 256>>>(ei);
    scan_kernel<<<1, 1024>>>();
    scatter_kernel<<<div_up(ET, 256), 256>>>(ei);
    prep_a_kernel<<<div_up(NPAD * 224, 256), 256>>>(X, 200, 224);
    prep_all_b_kernel<<<div_up(BTOT, 256), 256>>>(W[0], W[1], W[2], W[3], W[4]);

    const int HEADS[5] = {4, 4, 4, 4, 1};
    const int BOFF[5]  = {BOFF0, BOFF1, BOFF2, BOFF3, BOFF4};
    const int MT = NPAD / 128;   // 79 m-tiles

    for (int L = 0; L < 5; L++) {
        int H   = HEADS[L];
        int HC  = H * CC;
        int Kp  = (L == 0) ? 224 : 800;
        int NBT = div_up(HC, 80) * 80;   // 800 or 240

        int cur = L & 1, nxt = cur ^ 1;
        dim3 ggrid(MT, NBT / 80);
        gemm_mma_kernel<<<ggrid, 256, GEMM_SMEM>>>(
            pahi, palo, pbhi + BOFF[L], pblo + BOFF[L], ph,
            AS[L], AD[L], pasrc[cur], padst[cur],
            pasrc[nxt], padst[nxt],
            Kp, HC, H);

        float* outp  = (L == 4) ? out_x : nullptr;
        float* attnp = (L == 4) ? out_a : nullptr;
        __nv_bfloat16* hi_o = (L < 4) ? pahi : nullptr;
        __nv_bfloat16* lo_o = (L < 4) ? palo : nullptr;
        int nwarps = NN * H;
        agg_warp_kernel<<<div_up(nwarps * 32, 256), 256>>>(
            ph, Bb[L], pasrc[cur], padst[cur], outp, attnp, hi_o, lo_o, H, HC);
    }
    (void)in_sizes; (void)n_in; (void)out_size;
}